// round 14
// baseline (speedup 1.0000x reference)
#include <cuda_runtime.h>
#include <math.h>

#define NB 128
#define NLANE 32
#define NBINS 20
#define TPB 256
#define GRID 2664         // 148 SMs x 6 CTAs x 3 waves
#define NACC 40           // g_acc[0..19] = A~_j (no kappa), [20..39] = D~_j

#define CNT_SHIFT 23
#define CNT_INC (1u << CNT_SHIFT)
#define SUM_MASK ((1u << CNT_SHIFT) - 1u)
#define DS_SCALE 4096.0f           // 2^12
#define DS_INV (1.0f / 4096.0f)
#define DS_BIAS 8192               // 2^13 per element

__device__ double g_acc[NACC];
__device__ unsigned int g_count;

__device__ __forceinline__ float wred_f(float v) {
#pragma unroll
    for (int off = 16; off; off >>= 1)
        v += __shfl_down_sync(0xffffffffu, v, off);
    return v;
}

__global__ void __launch_bounds__(TPB, 6)
ace_hist_kernel(const float* __restrict__ preds,
                const float* __restrict__ targs,
                int n, float* __restrict__ out, int out_size) {
    // hist[b][lane]: lane L only touches bank L -> every REDS is 1 wavefront.
    __shared__ unsigned int hist[NB * NLANE];
    __shared__ float sCnt[NB], sDv[NB];
    __shared__ float smA[NBINS], smD[NBINS];
    const int tid = threadIdx.x;
    const int lane = tid & 31;

#pragma unroll
    for (int k = 0; k < (NB * NLANE) / TPB; k++) hist[tid + k * TPB] = 0u;
    if (tid < NBINS) { smA[tid] = 0.0f; smD[tid] = 0.0f; }
    __syncthreads();

    // ---- main loop: one conflict-free 32-bit shared atomic per element ----
    const int n4 = n >> 2;
    const float4* p4 = (const float4*)preds;
    const float4* t4 = (const float4*)targs;
    const int stride = gridDim.x * blockDim.x;
    int g = blockIdx.x * blockDim.x + tid;

    if (g < n4) {
        float4 pv = p4[g];
        float4 tv = t4[g];
        while (1) {
            int gn = g + stride;
            bool more = (gn < n4);
            float4 pn, tn;
            if (more) { pn = p4[gn]; tn = t4[gn]; }   // 1-ahead prefetch

#pragma unroll
            for (int e = 0; e < 4; e++) {
                float p = (e == 0) ? pv.x : (e == 1) ? pv.y : (e == 2) ? pv.z : pv.w;
                float t = (e == 0) ? tv.x : (e == 1) ? tv.y : (e == 2) ? tv.z : tv.w;
                int b = (int)(p * (float)NB);
                b = min(max(b, 0), NB - 1);
                int ds = __float2int_rn((p - t) * DS_SCALE);
                atomicAdd(&hist[(b << 5) + lane],
                          CNT_INC + (unsigned int)(ds + DS_BIAS));   // REDS.32, 1 wf
            }

            if (!more) break;
            pv = pn; tv = tn; g = gn;
        }
    }

    // ---- scalar tail (n % 4): CTA 0 folds into its own histogram ----
    {
        int base4 = n4 << 2;
        int rem = n - base4;
        if (blockIdx.x == 0 && tid < rem) {
            float p = preds[base4 + tid];
            float t = targs[base4 + tid];
            int b = min(max((int)(p * (float)NB), 0), NB - 1);
            int ds = __float2int_rn((p - t) * DS_SCALE);
            atomicAdd(&hist[(b << 5) + lane],
                      CNT_INC + (unsigned int)(ds + DS_BIAS));
        }
    }
    __syncthreads();

    // ---- stage 1: collapse 32 lane columns per bin -> per-bin totals ----
    // entry e = tid + k*TPB: b = e>>5, column = e&31 == lane.
    {
        int warp = tid >> 5;
#pragma unroll
        for (int k = 0; k < (NB * NLANE) / TPB; k++) {
            int b = warp + k * (TPB / 32);
            unsigned int v = hist[(b << 5) + lane];
            float cnt = (float)(v >> CNT_SHIFT);
            float Dv = ((float)(int)((v & SUM_MASK) - ((v >> CNT_SHIFT) << 13)))
                       * DS_INV;
            cnt = wred_f(cnt);
            Dv = wred_f(Dv);
            if (lane == 0) { sCnt[b] = cnt; sDv[b] = Dv; }
        }
    }
    __syncthreads();

    // ---- stage 2: fold 128 per-bin totals into 40 moments ----
    if (tid < NB) {
        float cnt = sCnt[tid];
        float Dv = sDv[tid];
        float cb = ((float)tid + 0.5f) * (1.0f / (float)NB);
        float w   = __expf(-10.0f * cb * cb);
        float rho = __expf(cb * (20.0f / 19.0f));
#pragma unroll
        for (int j = 0; j < NBINS; j++) {
            float a = wred_f(w * cnt);
            float d = wred_f(w * Dv);
            if (lane == 0) {
                atomicAdd(&smA[j], a);
                atomicAdd(&smD[j], d);
            }
            w *= rho;
        }
    }
    __syncthreads();

    if (tid < NACC) {
        double v = (tid < NBINS) ? (double)smA[tid] : (double)smD[tid - NBINS];
        atomicAdd(&g_acc[tid], v);
    }
    __syncthreads();

    // ---- last CTA finalizes ----
    __shared__ unsigned int s_is_last;
    if (tid == 0) {
        __threadfence();
        unsigned int old = atomicAdd(&g_count, 1u);
        s_is_last = (old == gridDim.x - 1) ? 1u : 0u;
    }
    __syncthreads();

    if (s_is_last) {
        __shared__ double sloss[NBINS];
        if (tid < NBINS) {
            __threadfence();
            double Aj = atomicAdd(&g_acc[tid], 0.0);
            double Dj = atomicAdd(&g_acc[NBINS + tid], 0.0);
            double cj = (double)tid / 19.0;
            double kappa = exp(-10.0 * cj * cj);
            double ws = kappa * Aj;
            sloss[tid] = (ws != 0.0) ? fabs(kappa * Dj) / (ws + 1e-8) : 0.0;
        }
        __syncthreads();
        if (tid == 0) {
            double loss = 0.0;
            for (int j = 0; j < NBINS; j++) loss += sloss[j];
            float res = (float)(loss / NBINS);
            for (int i = 0; i < out_size; i++) out[i] = res;
            for (int k = 0; k < NACC; k++) g_acc[k] = 0.0;
            g_count = 0u;
            __threadfence();
        }
    }
}

extern "C" void kernel_launch(void* const* d_in, const int* in_sizes, int n_in,
                              void* d_out, int out_size) {
    const float* preds = (const float*)d_in[0];
    const float* targs = (const float*)d_in[1];
    int n = in_sizes[0];
    ace_hist_kernel<<<GRID, TPB>>>(preds, targs, n, (float*)d_out, out_size);
}